// round 10
// baseline (speedup 1.0000x reference)
#include <cuda_runtime.h>
#include <cuda_bf16.h>

// Problem constants
#define B_  8
#define T_  32
#define S_  512
#define F_  128
#define K_  64
#define N_  200

// Tiling
#define SI  32          // s-tile
#define FI  8           // f-tile
#define NT  128         // threads per block (4 warps)
#define KC  16          // k's per pipeline chunk
#define NCHUNK (K_/KC)  // 4

// SMEM (bytes):
//   Vbuf:  2 x KC*FI*SI floats = 32768 (per-warp-sliced double buffer)
//   attnF: K*T floats          = 8192
//   stgU:  (T/2)*SI*10 ull     = 40960 (overlays everything after main loop)
#define SMEM_VBUF_BYTES  (KC*FI*SI*4)
#define SMEM_ATTN_BYTES  (K_*T_*4)
#define SMEM_TOTAL       (2*SMEM_VBUF_BYTES + SMEM_ATTN_BYTES)   // 40960

typedef unsigned long long ull;

// Packed f32x2 FMA: acc = v * a + acc   (lanes = two adjacent t's)
__device__ __forceinline__ void fma2(ull& acc, ull v, ull a) {
    asm("fma.rn.f32x2 %0, %1, %2, %0;" : "+l"(acc) : "l"(v), "l"(a));
}
// Duplicate one fp32 into both lanes of an f32x2 register pair.
__device__ __forceinline__ ull dup2(float w) {
    ull r;
    asm("mov.b64 %0, {%1, %1};" : "=l"(r) : "f"(w));
    return r;
}
// 16B async copy global -> shared
__device__ __forceinline__ void cp_async16(float* smem_dst, const float* gsrc) {
    unsigned s = (unsigned)__cvta_generic_to_shared(smem_dst);
    asm volatile("cp.async.cg.shared.global [%0], [%1], 16;" :: "r"(s), "l"(gsrc));
}
__device__ __forceinline__ void cp_commit() {
    asm volatile("cp.async.commit_group;");
}
template <int N>
__device__ __forceinline__ void cp_wait() {
    asm volatile("cp.async.wait_group %0;" :: "n"(N));
}

// ---------------------------------------------------------------------------
// Grid: (S/SI, F/FI, B) = (16,16,8) = 2048 blocks, 128 threads, 4 CTAs/SM.
// Warp w owns fl in {2w, 2w+1}; thread (sgl, fll): 2 s x 1 f x ALL 32 t.
// Each warp pipelines ITS OWN V rows with cp.async -> no main-loop barriers.
// ---------------------------------------------------------------------------
__global__ void __launch_bounds__(NT, 4)
fusion_kernel(const float* __restrict__ tgt,
              const float* __restrict__ V,
              const float* __restrict__ corr,
              const int*   __restrict__ tIdx,
              const int*   __restrict__ rIdx,
              float* __restrict__ out) {
    extern __shared__ char smem[];
    float* Vb[2] = { (float*)smem, (float*)(smem + SMEM_VBUF_BYTES) };
    float* attnF = (float*)(smem + 2 * SMEM_VBUF_BYTES);   // [K][T]
    ull*   stgU  = (ull*)smem;                              // overlay after loop

    const int b   = blockIdx.z;
    const int f0  = blockIdx.y * FI;
    const int s0  = blockIdx.x * SI;
    const int tid = threadIdx.x;
    const int wid  = tid >> 5;
    const int lane = tid & 31;

    const int flp = wid * 2;          // warp's fl pair {flp, flp+1}
    const int fll = lane >> 4;        // 0..1 : fl within pair
    const int sgl = lane & 15;        // 0..15: s-group (2 s each)
    const int fl  = flp + fll;
    const int sl  = sgl * 2;

    const float* Vg = V + (long)b * K_ * F_ * S_ + (long)f0 * S_ + s0;

    // Per-warp fill of its 2 fl rows for chunk c into stage st.
    // Per thread: 8 cp.async (KC*2 rows x 128B / (32 lanes x 16B)).
    auto fill = [&](int c, int st) {
        float* dst = Vb[st];
        const float* src = Vg + (long)c * KC * F_ * S_;
        #pragma unroll
        for (int i = lane; i < KC * 2 * 8; i += 32) {
            int k  = i >> 4;            // i / 16
            int fr = (i >> 3) & 1;      // fl_local
            int u  = i & 7;             // 16B unit within 128B row
            cp_async16(dst + ((k * FI) + flp + fr) * SI + u * 4,
                       src + ((long)k * F_ + f0 + flp + fr) * S_ - (long)f0 * S_
                           + (long)(flp + fr) * 0 + u * 4
                           + (long)(f0 + flp + fr) * 0);
        }
    };
    // NOTE: lambda above got convoluted; use explicit loop instead below.

    // --- prefetch chunk 0 (per warp, its own rows) ---
    {
        const float* src = Vg;
        #pragma unroll
        for (int i = lane; i < KC * 2 * 8; i += 32) {
            int k  = i >> 4;
            int fr = (i >> 3) & 1;
            int u  = i & 7;
            cp_async16(Vb[0] + (k * FI + flp + fr) * SI + u * 4,
                       src + ((long)k * F_ + flp + fr) * S_ + u * 4);
        }
        cp_commit();
    }

    // --- softmax: 4 warps x 8 t's each, gather from L2-hot corr ---
    {
        int c0 = rIdx[lane];
        int c1 = rIdx[lane + 32];
        #pragma unroll
        for (int t = wid; t < T_; t += 4) {
            int row = tIdx[b * T_ + t];
            float v0 = __ldg(corr + row * N_ + c0);
            float v1 = __ldg(corr + row * N_ + c1);
            float m = fmaxf(v0, v1);
            #pragma unroll
            for (int off = 16; off > 0; off >>= 1)
                m = fmaxf(m, __shfl_xor_sync(0xffffffffu, m, off));
            float e0 = expf(v0 - m);
            float e1 = expf(v1 - m);
            float s = e0 + e1;
            #pragma unroll
            for (int off = 16; off > 0; off >>= 1)
                s += __shfl_xor_sync(0xffffffffu, s, off);
            float inv = 1.0f / s;
            attnF[lane * T_ + t]        = e0 * inv;
            attnF[(lane + 32) * T_ + t] = e1 * inv;
        }
    }
    __syncthreads();   // attnF visible to all warps (only block barrier pre-loop)

    // --- main loop: per-warp double-buffered k-chunks, NO block barriers ---
    ull acc[16][2];
    #pragma unroll
    for (int p = 0; p < 16; ++p) { acc[p][0] = 0ULL; acc[p][1] = 0ULL; }

    #pragma unroll
    for (int c = 0; c < NCHUNK; ++c) {
        if (c + 1 < NCHUNK) {
            float* dst = Vb[(c + 1) & 1];
            const float* src = Vg + (long)(c + 1) * KC * F_ * S_;
            #pragma unroll
            for (int i = lane; i < KC * 2 * 8; i += 32) {
                int k  = i >> 4;
                int fr = (i >> 3) & 1;
                int u  = i & 7;
                cp_async16(dst + (k * FI + flp + fr) * SI + u * 4,
                           src + ((long)k * F_ + flp + fr) * S_ + u * 4);
            }
            cp_commit();
            cp_wait<1>();   // this thread's chunk-c group done
        } else {
            cp_wait<0>();
        }
        __syncwarp();       // all lanes' copies of chunk c visible warp-wide

        const float* Vc = Vb[c & 1];
        const float* aFc = attnF + c * KC * T_;
        #pragma unroll 8
        for (int k = 0; k < KC; ++k) {
            float2 vf = *(const float2*)(Vc + (k * FI + fl) * SI + sl);
            ull vd0 = dup2(vf.x), vd1 = dup2(vf.y);
            const float* aF = aFc + k * T_;
            // half 0: t 0..15
            {
                ulonglong2 a01 = *(const ulonglong2*)(aF);
                ulonglong2 a23 = *(const ulonglong2*)(aF + 4);
                ulonglong2 a45 = *(const ulonglong2*)(aF + 8);
                ulonglong2 a67 = *(const ulonglong2*)(aF + 12);
                fma2(acc[0][0], vd0, a01.x); fma2(acc[0][1], vd1, a01.x);
                fma2(acc[1][0], vd0, a01.y); fma2(acc[1][1], vd1, a01.y);
                fma2(acc[2][0], vd0, a23.x); fma2(acc[2][1], vd1, a23.x);
                fma2(acc[3][0], vd0, a23.y); fma2(acc[3][1], vd1, a23.y);
                fma2(acc[4][0], vd0, a45.x); fma2(acc[4][1], vd1, a45.x);
                fma2(acc[5][0], vd0, a45.y); fma2(acc[5][1], vd1, a45.y);
                fma2(acc[6][0], vd0, a67.x); fma2(acc[6][1], vd1, a67.x);
                fma2(acc[7][0], vd0, a67.y); fma2(acc[7][1], vd1, a67.y);
            }
            // half 1: t 16..31
            {
                ulonglong2 a01 = *(const ulonglong2*)(aF + 16);
                ulonglong2 a23 = *(const ulonglong2*)(aF + 20);
                ulonglong2 a45 = *(const ulonglong2*)(aF + 24);
                ulonglong2 a67 = *(const ulonglong2*)(aF + 28);
                fma2(acc[8][0],  vd0, a01.x); fma2(acc[8][1],  vd1, a01.x);
                fma2(acc[9][0],  vd0, a01.y); fma2(acc[9][1],  vd1, a01.y);
                fma2(acc[10][0], vd0, a23.x); fma2(acc[10][1], vd1, a23.x);
                fma2(acc[11][0], vd0, a23.y); fma2(acc[11][1], vd1, a23.y);
                fma2(acc[12][0], vd0, a45.x); fma2(acc[12][1], vd1, a45.x);
                fma2(acc[13][0], vd0, a45.y); fma2(acc[13][1], vd1, a45.y);
                fma2(acc[14][0], vd0, a67.x); fma2(acc[14][1], vd1, a67.x);
                fma2(acc[15][0], vd0, a67.y); fma2(acc[15][1], vd1, a67.y);
            }
        }
        // no block barrier: this warp's buffer slice is private to this warp
    }
    __syncthreads();   // all warps done (stg overlays Vb + attnF)

    // --- stage: stgU[tpair][s][10] (fl at 0..7, 2 pad) ---
    #pragma unroll
    for (int p = 0; p < 16; ++p) {
        #pragma unroll
        for (int si = 0; si < 2; ++si) {
            stgU[(p * SI + sl + si) * 10 + fl] = acc[p][si];
        }
    }
    __syncthreads();

    // --- epilogue: per iter read 4 ull (2 x LDS.128) -> two float4 RMW ---
    #pragma unroll
    for (int i = tid; i < (T_ / 2) * SI * 2; i += NT) {
        int g  = i & 1;
        int s  = (i >> 1) & (SI - 1);
        int tp = i >> 6;
        const ull* src = &stgU[(tp * SI + s) * 10 + 4 * g];
        ulonglong2 u0 = *(const ulonglong2*)(src);       // f = 4g, 4g+1
        ulonglong2 u1 = *(const ulonglong2*)(src + 2);   // f = 4g+2, 4g+3
        float2 p0 = *(const float2*)&u0.x;  // (t_even, t_odd)
        float2 p1 = *(const float2*)&u0.y;
        float2 p2 = *(const float2*)&u1.x;
        float2 p3 = *(const float2*)&u1.y;

        long gi0 = (((long)b * T_ + 2 * tp)     * S_ + s0 + s) * F_ + f0 + 4 * g;
        long gi1 = (((long)b * T_ + 2 * tp + 1) * S_ + s0 + s) * F_ + f0 + 4 * g;
        float4 t4, c4;
        t4 = *(const float4*)(tgt + gi0);
        c4.x = p0.x + t4.x; c4.y = p1.x + t4.y;
        c4.z = p2.x + t4.z; c4.w = p3.x + t4.w;
        *(float4*)(out + gi0) = c4;
        t4 = *(const float4*)(tgt + gi1);
        c4.x = p0.y + t4.x; c4.y = p1.y + t4.y;
        c4.z = p2.y + t4.z; c4.w = p3.y + t4.w;
        *(float4*)(out + gi1) = c4;
    }
}

// ---------------------------------------------------------------------------
extern "C" void kernel_launch(void* const* d_in, const int* in_sizes, int n_in,
                              void* d_out, int out_size) {
    const float* tgt  = nullptr;   // 16777216
    const float* V    = nullptr;   // 33554432
    const float* corr = nullptr;   // 40000
    const int*   tIdx = nullptr;   // 256   (int32: jax x64 disabled)
    const int*   rIdx = nullptr;   // 64

    for (int i = 0; i < n_in; ++i) {
        switch (in_sizes[i]) {
            case 16777216: tgt  = (const float*)d_in[i]; break;
            case 33554432: V    = (const float*)d_in[i]; break;
            case 40000:    corr = (const float*)d_in[i]; break;
            case 256:      tIdx = (const int*)d_in[i]; break;
            case 64:       rIdx = (const int*)d_in[i]; break;
            default: break;
        }
    }

    cudaFuncSetAttribute(fusion_kernel,
                         cudaFuncAttributeMaxDynamicSharedMemorySize,
                         SMEM_TOTAL);

    dim3 grid(S_ / SI, F_ / FI, B_);
    fusion_kernel<<<grid, NT, SMEM_TOTAL>>>(tgt, V, corr, tIdx, rIdx, (float*)d_out);
}